// round 16
// baseline (speedup 1.0000x reference)
#include <cuda_runtime.h>
#include <cuda_fp16.h>
#include <math.h>
#include <stdint.h>

// Problem constants
#define BB 4
#define SS 2048
#define DD 1024
#define HH 16
#define DK 64
#define MM (BB * SS)   // 8192 rows

// 0.125 (1/sqrt(DK)) * log2(e): folded into Q so softmax runs in log2 domain
#define SCALE_Q 0.1803368801111204f

// ---------------------------------------------------------------------------
// Scratch (static device globals: allocation-free per harness rules)
// ---------------------------------------------------------------------------
__device__ __align__(16) __half g_xh[MM * DD];
__device__ __align__(16) __half g_qh[MM * DD];
__device__ __align__(16) __half g_kh[MM * DD];
__device__ __align__(16) __half g_vh[MM * DD];
__device__ __align__(16) __half g_ch[MM * DD];
__device__ __align__(16) __half g_wh[4 * DD * DD];   // weights: fp16

// ---------------------------------------------------------------------------
// Low-level helpers (base ISA only: ldmatrix + mma.sync + cp.async)
// ---------------------------------------------------------------------------
__device__ __forceinline__ uint32_t smem_u32(const void* p) {
    uint32_t a;
    asm("{ .reg .u64 t; cvta.to.shared.u64 t, %1; cvt.u32.u64 %0, t; }"
        : "=r"(a) : "l"(p));
    return a;
}

__device__ __forceinline__ uint32_t sw128(uint32_t off) {
    return off ^ ((off >> 3) & 0x70);
}

__device__ __forceinline__ void cp16(uint32_t dst, const void* src) {
    asm volatile("cp.async.cg.shared.global [%0], [%1], 16;"
                 :: "r"(dst), "l"(src) : "memory");
}

__device__ __forceinline__ void ldsm_x4(uint32_t* r, uint32_t addr) {
    asm volatile("ldmatrix.sync.aligned.m8n8.x4.shared.b16 {%0,%1,%2,%3}, [%4];"
                 : "=r"(r[0]), "=r"(r[1]), "=r"(r[2]), "=r"(r[3]) : "r"(addr));
}

__device__ __forceinline__ void ldsm_x4t(uint32_t* r, uint32_t addr) {
    asm volatile("ldmatrix.sync.aligned.m8n8.x4.trans.shared.b16 {%0,%1,%2,%3}, [%4];"
                 : "=r"(r[0]), "=r"(r[1]), "=r"(r[2]), "=r"(r[3]) : "r"(addr));
}

// fp16 inputs, fp32 accumulate
__device__ __forceinline__ void mma16816(float* c, const uint32_t* a,
                                         const uint32_t* b) {
    asm volatile(
        "mma.sync.aligned.m16n8k16.row.col.f32.f16.f16.f32 "
        "{%0,%1,%2,%3}, {%4,%5,%6,%7}, {%8,%9}, {%0,%1,%2,%3};"
        : "+f"(c[0]), "+f"(c[1]), "+f"(c[2]), "+f"(c[3])
        : "r"(a[0]), "r"(a[1]), "r"(a[2]), "r"(a[3]), "r"(b[0]), "r"(b[1]));
}

__device__ __forceinline__ float ex2f(float x) {
    float r;
    asm("ex2.approx.ftz.f32 %0, %1;" : "=f"(r) : "f"(x));
    return r;
}

__device__ __forceinline__ uint32_t ex2_h2(uint32_t a) {
    uint32_t r;
    asm("ex2.approx.f16x2 %0, %1;" : "=r"(r) : "r"(a));
    return r;
}

__device__ __forceinline__ uint32_t pack_h2(float x, float y) {
    uint32_t h;
    asm("cvt.rn.f16x2.f32 %0, %1, %2;" : "=r"(h) : "f"(y), "f"(x));
    return h;
}

// ---------------------------------------------------------------------------
// Pack kernels. pack_x split in two launches keeps ncu capture slot (#3)
// on the QKV hgemm.
// ---------------------------------------------------------------------------
__global__ __launch_bounds__(256) void split_w(
    const float* __restrict__ W0, const float* __restrict__ W1,
    const float* __restrict__ W2, const float* __restrict__ W3,
    __half* __restrict__ out)
{
    int mat = blockIdx.x >> 10;
    int i = (blockIdx.x & 1023) * 256 + threadIdx.x;
    const float* src = (mat == 0) ? W0 : (mat == 1) ? W1 : (mat == 2) ? W2 : W3;
    float4 v = reinterpret_cast<const float4*>(src)[i];
    uint32_t* dst = reinterpret_cast<uint32_t*>(out + (size_t)mat * DD * DD);
    dst[2 * i]     = pack_h2(v.x, v.y);
    dst[2 * i + 1] = pack_h2(v.z, v.w);
}

__global__ __launch_bounds__(256) void pack_x(
    const float* __restrict__ src, __half* __restrict__ dst)
{
    int i = blockIdx.x * 256 + threadIdx.x;
    float4 v = reinterpret_cast<const float4*>(src)[i];
    reinterpret_cast<uint32_t*>(dst)[2 * i]     = pack_h2(v.x, v.y);
    reinterpret_cast<uint32_t*>(dst)[2 * i + 1] = pack_h2(v.z, v.w);
}

// ---------------------------------------------------------------------------
// fp16 GEMM (NT), fused over up to 3 weight matrices (mat = blockIdx.x>>3):
//   C[m,n] = (Ah[m,:] . Wh[n,:] + bias[n]) * scale
// CTA 128x128, BK=64, 128 threads (4 warps, 2x2), warp tile 64x64,
// 3-stage cp.async, 2 CTAs/SM, REGISTER-LEVEL FRAGMENT DOUBLE BUFFERING:
// k16+1's LDSMs issue before k16's 32 MMAs, hiding the LDS latency that
// stalled both resident warps at every k16 boundary (tensor was 57.7%).
// ---------------------------------------------------------------------------
#define G_STAGE 32768   // Ah 16K | Wh 16K
#define G_SMEM  (3 * G_STAGE)

template<bool F32OUT>
__global__ __launch_bounds__(128, 2) void hgemm(
    const __half* __restrict__ Ah,
    const __half* __restrict__ Wh,
    const float* __restrict__ B0, const float* __restrict__ B1,
    const float* __restrict__ B2,
    __half* __restrict__ O0h, __half* __restrict__ O1h,
    __half* __restrict__ O2h,
    float* __restrict__ Cf)
{
    extern __shared__ __align__(1024) char smem[];
    uint32_t sb = smem_u32(smem);
    const int tid = threadIdx.x;
    const int w = tid >> 5, lane = tid & 31;
    const int wr = w >> 1, wc = w & 1;          // 2x2 warp grid, 64x64 tiles
    const int mat = blockIdx.x >> 3;
    const int n0  = (blockIdx.x & 7) * 128;
    const int m0  = blockIdx.y * 128;
    const __half* Wmh = Wh + (size_t)mat * DD * DD;

    float acc[4][8][4];
    #pragma unroll
    for (int mt = 0; mt < 4; mt++)
        #pragma unroll
        for (int nt = 0; nt < 8; nt++)
            #pragma unroll
            for (int i = 0; i < 4; i++) acc[mt][nt][i] = 0.f;

    auto load_stage = [&](int t, int s) {
        uint32_t base = sb + s * G_STAGE;
        #pragma unroll
        for (int i = 0; i < 8; i++) {
            int idx = tid + i * 128;           // 0..1023
            int row = idx >> 3, c = idx & 7;
            cp16(base + sw128((uint32_t)idx * 16),
                 (const char*)Ah + (size_t)(m0 + row) * 2048 + t * 128 + c * 16);
            cp16(base + 16384u + sw128((uint32_t)idx * 16),
                 (const char*)Wmh + (size_t)(n0 + row) * 2048 + t * 128 + c * 16);
        }
        asm volatile("cp.async.commit_group;" ::: "memory");
    };

    // load all fragments for one k16 slice from stage `base`
    auto load_frags = [&](uint32_t base, int k16,
                          uint32_t af[4][4], uint32_t bf[8][2]) {
        #pragma unroll
        for (int mt = 0; mt < 4; mt++) {
            int row = wr * 64 + mt * 16 + (lane & 15);
            uint32_t off = sw128((uint32_t)row * 128 +
                                 (k16 * 2 + (lane >> 4)) * 16);
            ldsm_x4(af[mt], base + off);
        }
        #pragma unroll
        for (int nh = 0; nh < 4; nh++) {
            int row = wc * 64 + nh * 16 + (lane & 15);
            uint32_t off = sw128((uint32_t)row * 128 +
                                 (k16 * 2 + (lane >> 4)) * 16);
            uint32_t r[4];
            ldsm_x4(r, base + 16384u + off);
            bf[nh * 2][0] = r[0]; bf[nh * 2 + 1][0] = r[1];
            bf[nh * 2][1] = r[2]; bf[nh * 2 + 1][1] = r[3];
        }
    };

    const int NT = DD / 64;  // 16
    load_stage(0, 0);
    load_stage(1, 1);

    uint32_t af[2][4][4], bf[2][8][2];

    for (int t = 0; t < NT; t++) {
        if (t < NT - 1)
            asm volatile("cp.async.wait_group 1;" ::: "memory");
        else
            asm volatile("cp.async.wait_group 0;" ::: "memory");
        __syncthreads();
        if (t + 2 < NT) load_stage(t + 2, (t + 2) % 3);
        uint32_t base = sb + (t % 3) * G_STAGE;

        load_frags(base, 0, af[0], bf[0]);
        #pragma unroll
        for (int k16 = 0; k16 < 4; k16++) {
            int cur = k16 & 1, nxt = cur ^ 1;
            if (k16 < 3) load_frags(base, k16 + 1, af[nxt], bf[nxt]);
            #pragma unroll
            for (int mt = 0; mt < 4; mt++)
                #pragma unroll
                for (int nt = 0; nt < 8; nt++)
                    mma16816(acc[mt][nt], af[cur][mt], bf[cur][nt]);
        }
    }

    // Epilogue
    const float* bias = (mat == 0) ? B0 : (mat == 1 ? B1 : B2);
    __half* Oh = (mat == 0) ? O0h : (mat == 1 ? O1h : O2h);
    const float scl = (!F32OUT && mat == 0) ? SCALE_Q : 1.0f;
    const int r = lane >> 2, cp2 = (lane & 3) * 2;
    #pragma unroll
    for (int mt = 0; mt < 4; mt++) {
        #pragma unroll
        for (int nt = 0; nt < 8; nt++) {
            int row = m0 + wr * 64 + mt * 16 + r;
            int col = n0 + wc * 64 + nt * 8 + cp2;
            float b0 = bias[col], b1 = bias[col + 1];
            float v00 = (acc[mt][nt][0] + b0) * scl;
            float v01 = (acc[mt][nt][1] + b1) * scl;
            float v10 = (acc[mt][nt][2] + b0) * scl;
            float v11 = (acc[mt][nt][3] + b1) * scl;
            if (F32OUT) {
                *reinterpret_cast<float2*>(Cf + (size_t)row * DD + col) =
                    make_float2(v00, v01);
                *reinterpret_cast<float2*>(Cf + (size_t)(row + 8) * DD + col) =
                    make_float2(v10, v11);
            } else {
                *reinterpret_cast<uint32_t*>(Oh + (size_t)row * DD + col) =
                    pack_h2(v00, v01);
                *reinterpret_cast<uint32_t*>(Oh + (size_t)(row + 8) * DD + col) =
                    pack_h2(v10, v11);
            }
        }
    }
}

// ---------------------------------------------------------------------------
// Flash attention — R15 version (proven): single-chain fp16, R9 ordering,
// super-iterations (2 x 64-KV subtiles per sync), Q in regs, 2 CTAs/SM.
// ---------------------------------------------------------------------------
#define A_STAGE 16384   // Kh 8K | Vh 8K per 64-KV subtile
#define A_SMEM  (4 * A_STAGE + 16384)   // 4 stages + Q staging (80 KB)

__global__ __launch_bounds__(256, 2) void attn_mma(
    const __half* __restrict__ Qh,
    const __half* __restrict__ Kh,
    const __half* __restrict__ Vh,
    __half* __restrict__ Ch)
{
    extern __shared__ __align__(1024) char smem[];
    uint32_t sb = smem_u32(smem);
    const uint32_t qreg = sb + 4 * A_STAGE;
    const int tid = threadIdx.x;
    const int w = tid >> 5, lane = tid & 31;
    const int q0 = blockIdx.x * 128;
    const int hd = blockIdx.y;
    const int b  = blockIdx.z;

    const size_t qbase = ((size_t)b * SS + q0) * DD + hd * 64;
    const size_t kbase = (size_t)b * SS * DD + hd * 64;

    auto load_kv = [&](int it, int s) {
        uint32_t base = sb + s * A_STAGE;
        const char* gk = (const char*)Kh + (kbase + (size_t)it * 64 * DD) * 2;
        const char* gv = (const char*)Vh + (kbase + (size_t)it * 64 * DD) * 2;
        #pragma unroll
        for (int i = 0; i < 2; i++) {
            int idx = tid + i * 256;       // 0..511
            int row = idx >> 3, c = idx & 7;
            cp16(base + sw128((uint32_t)idx * 16),
                 gk + (size_t)row * 2048 + c * 16);
            cp16(base + 8192u + sw128((uint32_t)idx * 16),
                 gv + (size_t)row * 2048 + c * 16);
        }
    };
    auto load_super = [&](int t, int buf) {
        load_kv(2 * t,     buf * 2);
        load_kv(2 * t + 1, buf * 2 + 1);
        asm volatile("cp.async.commit_group;" ::: "memory");
    };

    // ---- Prologue: Q -> qreg (group 0); super 0 in flight (group 1) ----
    {
        const char* gq = (const char*)Qh + qbase * 2;
        #pragma unroll
        for (int i = 0; i < 4; i++) {
            int idx = tid + i * 256;       // 0..1023
            int row = idx >> 3, c = idx & 7;
            cp16(qreg + sw128((uint32_t)idx * 16),
                 gq + (size_t)row * 2048 + c * 16);
        }
        asm volatile("cp.async.commit_group;" ::: "memory");
    }
    load_super(0, 0);

    asm volatile("cp.async.wait_group 1;" ::: "memory");  // Q landed
    __syncthreads();
    uint32_t qf[4][4];
    #pragma unroll
    for (int k16 = 0; k16 < 4; k16++) {
        int row = w * 16 + (lane & 15);
        uint32_t off = sw128((uint32_t)row * 128 +
                             (k16 * 2 + (lane >> 4)) * 16);
        ldsm_x4(qf[k16], qreg + off);
    }

    float o[8][4];
    #pragma unroll
    for (int dt = 0; dt < 8; dt++)
        #pragma unroll
        for (int i = 0; i < 4; i++) o[dt][i] = 0.f;
    float lacc[4] = {0.f, 0.f, 0.f, 0.f};
    const float NEG_INF = __int_as_float(0xff800000);
    float mrow[2] = {NEG_INF, NEG_INF};
    const uint32_t ONE_H2 = 0x3C003C00u;
    const uint32_t onef[2] = {ONE_H2, ONE_H2};

    const int NSUP = SS / 128;  // 16 super-iterations
    for (int j = 0; j < NSUP; j++) {
        asm volatile("cp.async.wait_group 0;" ::: "memory");  // super j landed
        __syncthreads();
        if (j + 1 < NSUP) load_super(j + 1, (j + 1) & 1);

        #pragma unroll
        for (int sub = 0; sub < 2; sub++) {
            uint32_t base = sb + ((j & 1) * 2 + sub) * A_STAGE;

            // ---- S = Q K^T ----
            float s[8][4];
            #pragma unroll
            for (int nt = 0; nt < 8; nt++)
                #pragma unroll
                for (int i = 0; i < 4; i++) s[nt][i] = 0.f;

            #pragma unroll
            for (int k16 = 0; k16 < 4; k16++) {
                uint32_t kf[8][2];
                #pragma unroll
                for (int nh = 0; nh < 4; nh++) {
                    int row = nh * 16 + (lane & 15);
                    uint32_t off = sw128((uint32_t)row * 128 +
                                         (k16 * 2 + (lane >> 4)) * 16);
                    uint32_t r[4];
                    ldsm_x4(r, base + off);
                    kf[nh * 2][0] = r[0]; kf[nh * 2 + 1][0] = r[1];
                    kf[nh * 2][1] = r[2]; kf[nh * 2 + 1][1] = r[3];
                }
                #pragma unroll
                for (int nt = 0; nt < 8; nt++)
                    mma16816(s[nt], qf[k16], kf[nt]);
            }

            // ---- softmax (log2 domain; exp in f16x2 -> P frags) ----
            uint32_t pp[16];
            #pragma unroll
            for (int hf = 0; hf < 2; hf++) {
                float mx = NEG_INF;
                #pragma unroll
                for (int nt = 0; nt < 8; nt++)
                    mx = fmaxf(mx, fmaxf(s[nt][2 * hf], s[nt][2 * hf + 1]));
                mx = fmaxf(mx, __shfl_xor_sync(0xffffffffu, mx, 1));
                mx = fmaxf(mx, __shfl_xor_sync(0xffffffffu, mx, 2));
                float mn = fmaxf(mrow[hf], mx);
                uint32_t keep = __all_sync(0xffffffffu, mn == mrow[hf]);
                if (!keep) {
                    float scale = ex2f(mrow[hf] - mn);
                    mrow[hf] = mn;
                    #pragma unroll
                    for (int dt = 0; dt < 8; dt++) {
                        o[dt][2 * hf]     *= scale;
                        o[dt][2 * hf + 1] *= scale;
                    }
                    lacc[2 * hf]     *= scale;
                    lacc[2 * hf + 1] *= scale;
                }
                #pragma unroll
                for (int nt = 0; nt < 8; nt++) {
                    uint32_t u = pack_h2(s[nt][2 * hf] - mn,
                                         s[nt][2 * hf + 1] - mn);
                    pp[4 * (nt >> 1) + (nt & 1) * 2 + hf] = ex2_h2(u);
                }
            }

            // ---- O += P V, l += P . 1 ----
            #pragma unroll
            for (int t = 0; t < 4; t++) {
                uint32_t vf[8][2];
                #pragma unroll
                for (int dp = 0; dp < 4; dp++) {
                    int row = t * 16 + (lane & 15);
                    uint32_t off = sw128((uint32_t)row * 128 +
                                         (dp * 2 + (lane >> 4)) * 16);
                    uint32_t r[4];
                    ldsm_x4t(r, base + 8192u + off);
                    vf[dp * 2][0] = r[0]; vf[dp * 2][1] = r[1];
                    vf[dp * 2 + 1][0] = r[2]; vf[dp * 2 + 1][1] = r[3];
                }
                #pragma unroll
                for (int dt = 0; dt < 8; dt++)
                    mma16816(o[dt], &pp[4 * t], vf[dt]);
                mma16816(lacc, &pp[4 * t], onef);
            }
        }
    }

    // ---- epilogue: ctx = O / l, written as fp16 ----
    const int r = lane >> 2, cp2 = (lane & 3) * 2;
    #pragma unroll
    for (int hf = 0; hf < 2; hf++) {
        float inv = 1.f / lacc[2 * hf];
        int row = q0 + w * 16 + r + hf * 8;
        size_t ob = ((size_t)b * SS + row) * DD + hd * 64;
        #pragma unroll
        for (int dt = 0; dt < 8; dt++) {
            float v0 = o[dt][2 * hf] * inv;
            float v1 = o[dt][2 * hf + 1] * inv;
            *reinterpret_cast<uint32_t*>(Ch + ob + dt * 8 + cp2) =
                pack_h2(v0, v1);
        }
    }
}

// ---------------------------------------------------------------------------
// Launch (pack_x split in two so ncu's captured launch #3 = QKV hgemm)
// ---------------------------------------------------------------------------
extern "C" void kernel_launch(void* const* d_in, const int* in_sizes, int n_in,
                              void* d_out, int out_size)
{
    const float* x  = (const float*)d_in[0];
    const float* Wq = (const float*)d_in[1];
    const float* bq = (const float*)d_in[2];
    const float* Wk = (const float*)d_in[3];
    const float* bk = (const float*)d_in[4];
    const float* Wv = (const float*)d_in[5];
    const float* bv = (const float*)d_in[6];
    const float* Wo = (const float*)d_in[7];
    const float* bo = (const float*)d_in[8];
    float* out = (float*)d_out;

    __half *xh, *qh, *kh, *vh, *ch, *wh;
    cudaGetSymbolAddress((void**)&xh, g_xh);
    cudaGetSymbolAddress((void**)&qh, g_qh);
    cudaGetSymbolAddress((void**)&kh, g_kh);
    cudaGetSymbolAddress((void**)&vh, g_vh);
    cudaGetSymbolAddress((void**)&ch, g_ch);
    cudaGetSymbolAddress((void**)&wh, g_wh);

    cudaFuncSetAttribute((const void*)hgemm<false>,
                         cudaFuncAttributeMaxDynamicSharedMemorySize, G_SMEM);
    cudaFuncSetAttribute((const void*)hgemm<true>,
                         cudaFuncAttributeMaxDynamicSharedMemorySize, G_SMEM);
    cudaFuncSetAttribute((const void*)attn_mma,
                         cudaFuncAttributeMaxDynamicSharedMemorySize, A_SMEM);

    // launch 0: all weights -> fp16
    split_w<<<4096, 256>>>(Wq, Wk, Wv, Wo, wh);
    // launches 1+2: x -> fp16 (two halves)
    const int HALF = MM * DD / 2;
    pack_x<<<4096, 256>>>(x, xh);
    pack_x<<<4096, 256>>>(x + HALF, xh + HALF);

    // launch 3: fused QKV projection  (ncu capture slot)
    dim3 gqkv(24, 64);
    hgemm<false><<<gqkv, 128, G_SMEM>>>(
        xh, wh, bq, bk, bv, qh, kh, vh, nullptr);

    // launch 4: attention
    dim3 ag(SS / 128, HH, BB);    // (16, 16, 4)
    attn_mma<<<ag, 256, A_SMEM>>>(qh, kh, vh, ch);

    // launch 5: output projection (fp32 out, single fp16 chain)
    dim3 go(8, 64);
    hgemm<true><<<go, 128, G_SMEM>>>(
        ch, wh + 3 * (size_t)DD * DD, bo, nullptr, nullptr,
        nullptr, nullptr, nullptr, out);
}

// round 17
// speedup vs baseline: 1.0381x; 1.0381x over previous
#include <cuda_runtime.h>
#include <cuda_fp16.h>
#include <math.h>
#include <stdint.h>

// Problem constants
#define BB 4
#define SS 2048
#define DD 1024
#define HH 16
#define DK 64
#define MM (BB * SS)   // 8192 rows

// 0.125 (1/sqrt(DK)) * log2(e): folded into Q so softmax runs in log2 domain
#define SCALE_Q 0.1803368801111204f

// ---------------------------------------------------------------------------
// Scratch (static device globals: allocation-free per harness rules)
// ---------------------------------------------------------------------------
__device__ __align__(16) __half g_xh[MM * DD];
__device__ __align__(16) __half g_qh[MM * DD];
__device__ __align__(16) __half g_kh[MM * DD];
__device__ __align__(16) __half g_vh[MM * DD];
__device__ __align__(16) __half g_ch[MM * DD];
__device__ __align__(16) __half g_wh[4 * DD * DD];   // weights: fp16

// ---------------------------------------------------------------------------
// Low-level helpers (base ISA only: ldmatrix + mma.sync + cp.async)
// ---------------------------------------------------------------------------
__device__ __forceinline__ uint32_t smem_u32(const void* p) {
    uint32_t a;
    asm("{ .reg .u64 t; cvta.to.shared.u64 t, %1; cvt.u32.u64 %0, t; }"
        : "=r"(a) : "l"(p));
    return a;
}

__device__ __forceinline__ uint32_t sw128(uint32_t off) {
    return off ^ ((off >> 3) & 0x70);
}

__device__ __forceinline__ void cp16(uint32_t dst, const void* src) {
    asm volatile("cp.async.cg.shared.global [%0], [%1], 16;"
                 :: "r"(dst), "l"(src) : "memory");
}

__device__ __forceinline__ void ldsm_x4(uint32_t* r, uint32_t addr) {
    asm volatile("ldmatrix.sync.aligned.m8n8.x4.shared.b16 {%0,%1,%2,%3}, [%4];"
                 : "=r"(r[0]), "=r"(r[1]), "=r"(r[2]), "=r"(r[3]) : "r"(addr));
}

__device__ __forceinline__ void ldsm_x4t(uint32_t* r, uint32_t addr) {
    asm volatile("ldmatrix.sync.aligned.m8n8.x4.trans.shared.b16 {%0,%1,%2,%3}, [%4];"
                 : "=r"(r[0]), "=r"(r[1]), "=r"(r[2]), "=r"(r[3]) : "r"(addr));
}

// fp16 inputs, fp32 accumulate
__device__ __forceinline__ void mma16816(float* c, const uint32_t* a,
                                         const uint32_t* b) {
    asm volatile(
        "mma.sync.aligned.m16n8k16.row.col.f32.f16.f16.f32 "
        "{%0,%1,%2,%3}, {%4,%5,%6,%7}, {%8,%9}, {%0,%1,%2,%3};"
        : "+f"(c[0]), "+f"(c[1]), "+f"(c[2]), "+f"(c[3])
        : "r"(a[0]), "r"(a[1]), "r"(a[2]), "r"(a[3]), "r"(b[0]), "r"(b[1]));
}

// fp16 inputs, fp16 accumulate (rate probe: possibly 2x fp32-accum)
__device__ __forceinline__ void mma16816h(uint32_t* c, const uint32_t* a,
                                          const uint32_t* b) {
    asm volatile(
        "mma.sync.aligned.m16n8k16.row.col.f16.f16.f16.f16 "
        "{%0,%1}, {%2,%3,%4,%5}, {%6,%7}, {%0,%1};"
        : "+r"(c[0]), "+r"(c[1])
        : "r"(a[0]), "r"(a[1]), "r"(a[2]), "r"(a[3]), "r"(b[0]), "r"(b[1]));
}

__device__ __forceinline__ float ex2f(float x) {
    float r;
    asm("ex2.approx.ftz.f32 %0, %1;" : "=f"(r) : "f"(x));
    return r;
}

__device__ __forceinline__ uint32_t ex2_h2(uint32_t a) {
    uint32_t r;
    asm("ex2.approx.f16x2 %0, %1;" : "=r"(r) : "r"(a));
    return r;
}

__device__ __forceinline__ uint32_t pack_h2(float x, float y) {
    uint32_t h;
    asm("cvt.rn.f16x2.f32 %0, %1, %2;" : "=r"(h) : "f"(y), "f"(x));
    return h;
}

// ---------------------------------------------------------------------------
// Single fused pack kernel: W0..W3 -> wh, x -> xh. One launch.
// Blocks [0,4096): weights (1024 blocks per matrix). Blocks [4096,12288): x.
// ---------------------------------------------------------------------------
__global__ __launch_bounds__(256) void pack_all(
    const float* __restrict__ W0, const float* __restrict__ W1,
    const float* __restrict__ W2, const float* __restrict__ W3,
    const float* __restrict__ x,
    __half* __restrict__ wh, __half* __restrict__ xh)
{
    int blk = blockIdx.x;
    const float* src;
    uint32_t* dst;
    int i;
    if (blk < 4096) {
        int mat = blk >> 10;
        i = (blk & 1023) * 256 + threadIdx.x;
        src = (mat == 0) ? W0 : (mat == 1) ? W1 : (mat == 2) ? W2 : W3;
        dst = reinterpret_cast<uint32_t*>(wh + (size_t)mat * DD * DD);
    } else {
        i = (blk - 4096) * 256 + threadIdx.x;
        src = x;
        dst = reinterpret_cast<uint32_t*>(xh);
    }
    float4 v = reinterpret_cast<const float4*>(src)[i];
    dst[2 * i]     = pack_h2(v.x, v.y);
    dst[2 * i + 1] = pack_h2(v.z, v.w);
}

// ---------------------------------------------------------------------------
// fp16 GEMM (NT), fused over up to 3 weight matrices (mat = blockIdx.x>>3):
//   C[m,n] = (Ah[m,:] . Wh[n,:] + bias[n]) * scale
// CTA 128x128, BK=64, 128 threads (4 warps, 2x2), warp tile 64x64,
// 3-stage cp.async, 2 CTAs/SM, fragment double-buffering. (R16, unchanged)
// ---------------------------------------------------------------------------
#define G_STAGE 32768   // Ah 16K | Wh 16K
#define G_SMEM  (3 * G_STAGE)

template<bool F32OUT>
__global__ __launch_bounds__(128, 2) void hgemm(
    const __half* __restrict__ Ah,
    const __half* __restrict__ Wh,
    const float* __restrict__ B0, const float* __restrict__ B1,
    const float* __restrict__ B2,
    __half* __restrict__ O0h, __half* __restrict__ O1h,
    __half* __restrict__ O2h,
    float* __restrict__ Cf)
{
    extern __shared__ __align__(1024) char smem[];
    uint32_t sb = smem_u32(smem);
    const int tid = threadIdx.x;
    const int w = tid >> 5, lane = tid & 31;
    const int wr = w >> 1, wc = w & 1;          // 2x2 warp grid, 64x64 tiles
    const int mat = blockIdx.x >> 3;
    const int n0  = (blockIdx.x & 7) * 128;
    const int m0  = blockIdx.y * 128;
    const __half* Wmh = Wh + (size_t)mat * DD * DD;

    float acc[4][8][4];
    #pragma unroll
    for (int mt = 0; mt < 4; mt++)
        #pragma unroll
        for (int nt = 0; nt < 8; nt++)
            #pragma unroll
            for (int i = 0; i < 4; i++) acc[mt][nt][i] = 0.f;

    auto load_stage = [&](int t, int s) {
        uint32_t base = sb + s * G_STAGE;
        #pragma unroll
        for (int i = 0; i < 8; i++) {
            int idx = tid + i * 128;           // 0..1023
            int row = idx >> 3, c = idx & 7;
            cp16(base + sw128((uint32_t)idx * 16),
                 (const char*)Ah + (size_t)(m0 + row) * 2048 + t * 128 + c * 16);
            cp16(base + 16384u + sw128((uint32_t)idx * 16),
                 (const char*)Wmh + (size_t)(n0 + row) * 2048 + t * 128 + c * 16);
        }
        asm volatile("cp.async.commit_group;" ::: "memory");
    };

    auto load_frags = [&](uint32_t base, int k16,
                          uint32_t af[4][4], uint32_t bf[8][2]) {
        #pragma unroll
        for (int mt = 0; mt < 4; mt++) {
            int row = wr * 64 + mt * 16 + (lane & 15);
            uint32_t off = sw128((uint32_t)row * 128 +
                                 (k16 * 2 + (lane >> 4)) * 16);
            ldsm_x4(af[mt], base + off);
        }
        #pragma unroll
        for (int nh = 0; nh < 4; nh++) {
            int row = wc * 64 + nh * 16 + (lane & 15);
            uint32_t off = sw128((uint32_t)row * 128 +
                                 (k16 * 2 + (lane >> 4)) * 16);
            uint32_t r[4];
            ldsm_x4(r, base + 16384u + off);
            bf[nh * 2][0] = r[0]; bf[nh * 2 + 1][0] = r[1];
            bf[nh * 2][1] = r[2]; bf[nh * 2 + 1][1] = r[3];
        }
    };

    const int NT = DD / 64;  // 16
    load_stage(0, 0);
    load_stage(1, 1);

    uint32_t af[2][4][4], bf[2][8][2];

    for (int t = 0; t < NT; t++) {
        if (t < NT - 1)
            asm volatile("cp.async.wait_group 1;" ::: "memory");
        else
            asm volatile("cp.async.wait_group 0;" ::: "memory");
        __syncthreads();
        if (t + 2 < NT) load_stage(t + 2, (t + 2) % 3);
        uint32_t base = sb + (t % 3) * G_STAGE;

        load_frags(base, 0, af[0], bf[0]);
        #pragma unroll
        for (int k16 = 0; k16 < 4; k16++) {
            int cur = k16 & 1, nxt = cur ^ 1;
            if (k16 < 3) load_frags(base, k16 + 1, af[nxt], bf[nxt]);
            #pragma unroll
            for (int mt = 0; mt < 4; mt++)
                #pragma unroll
                for (int nt = 0; nt < 8; nt++)
                    mma16816(acc[mt][nt], af[cur][mt], bf[cur][nt]);
        }
    }

    // Epilogue
    const float* bias = (mat == 0) ? B0 : (mat == 1 ? B1 : B2);
    __half* Oh = (mat == 0) ? O0h : (mat == 1 ? O1h : O2h);
    const float scl = (!F32OUT && mat == 0) ? SCALE_Q : 1.0f;
    const int r = lane >> 2, cp2 = (lane & 3) * 2;
    #pragma unroll
    for (int mt = 0; mt < 4; mt++) {
        #pragma unroll
        for (int nt = 0; nt < 8; nt++) {
            int row = m0 + wr * 64 + mt * 16 + r;
            int col = n0 + wc * 64 + nt * 8 + cp2;
            float b0 = bias[col], b1 = bias[col + 1];
            float v00 = (acc[mt][nt][0] + b0) * scl;
            float v01 = (acc[mt][nt][1] + b1) * scl;
            float v10 = (acc[mt][nt][2] + b0) * scl;
            float v11 = (acc[mt][nt][3] + b1) * scl;
            if (F32OUT) {
                *reinterpret_cast<float2*>(Cf + (size_t)row * DD + col) =
                    make_float2(v00, v01);
                *reinterpret_cast<float2*>(Cf + (size_t)(row + 8) * DD + col) =
                    make_float2(v10, v11);
            } else {
                *reinterpret_cast<uint32_t*>(Oh + (size_t)row * DD + col) =
                    pack_h2(v00, v01);
                *reinterpret_cast<uint32_t*>(Oh + (size_t)(row + 8) * DD + col) =
                    pack_h2(v10, v11);
            }
        }
    }
}

// ---------------------------------------------------------------------------
// Flash attention: S-GEMM in fp16 ACCUMULATION (rate probe; error ~5e-4 abs
// in log2 units over the 4-step K=64 reduction, and the common-mode P error
// cancels in O/l since l uses the same fp16 P). Softmax runs natively on the
// fp16 fragments: hmax2 tree + hsub2 + ex2.f16x2 -> P frags directly.
// PV + l stay fp32-accum. R15 super-iteration structure, 2 CTAs/SM.
// ---------------------------------------------------------------------------
#define A_STAGE 16384   // Kh 8K | Vh 8K per 64-KV subtile
#define A_SMEM  (4 * A_STAGE + 16384)   // 4 stages + Q staging (80 KB)

__global__ __launch_bounds__(256, 2) void attn_mma(
    const __half* __restrict__ Qh,
    const __half* __restrict__ Kh,
    const __half* __restrict__ Vh,
    __half* __restrict__ Ch)
{
    extern __shared__ __align__(1024) char smem[];
    uint32_t sb = smem_u32(smem);
    const uint32_t qreg = sb + 4 * A_STAGE;
    const int tid = threadIdx.x;
    const int w = tid >> 5, lane = tid & 31;
    const int q0 = blockIdx.x * 128;
    const int hd = blockIdx.y;
    const int b  = blockIdx.z;

    const size_t qbase = ((size_t)b * SS + q0) * DD + hd * 64;
    const size_t kbase = (size_t)b * SS * DD + hd * 64;

    auto load_kv = [&](int it, int s) {
        uint32_t base = sb + s * A_STAGE;
        const char* gk = (const char*)Kh + (kbase + (size_t)it * 64 * DD) * 2;
        const char* gv = (const char*)Vh + (kbase + (size_t)it * 64 * DD) * 2;
        #pragma unroll
        for (int i = 0; i < 2; i++) {
            int idx = tid + i * 256;       // 0..511
            int row = idx >> 3, c = idx & 7;
            cp16(base + sw128((uint32_t)idx * 16),
                 gk + (size_t)row * 2048 + c * 16);
            cp16(base + 8192u + sw128((uint32_t)idx * 16),
                 gv + (size_t)row * 2048 + c * 16);
        }
    };
    auto load_super = [&](int t, int buf) {
        load_kv(2 * t,     buf * 2);
        load_kv(2 * t + 1, buf * 2 + 1);
        asm volatile("cp.async.commit_group;" ::: "memory");
    };

    // ---- Prologue: Q -> qreg (group 0); super 0 in flight (group 1) ----
    {
        const char* gq = (const char*)Qh + qbase * 2;
        #pragma unroll
        for (int i = 0; i < 4; i++) {
            int idx = tid + i * 256;       // 0..1023
            int row = idx >> 3, c = idx & 7;
            cp16(qreg + sw128((uint32_t)idx * 16),
                 gq + (size_t)row * 2048 + c * 16);
        }
        asm volatile("cp.async.commit_group;" ::: "memory");
    }
    load_super(0, 0);

    asm volatile("cp.async.wait_group 1;" ::: "memory");  // Q landed
    __syncthreads();
    uint32_t qf[4][4];
    #pragma unroll
    for (int k16 = 0; k16 < 4; k16++) {
        int row = w * 16 + (lane & 15);
        uint32_t off = sw128((uint32_t)row * 128 +
                             (k16 * 2 + (lane >> 4)) * 16);
        ldsm_x4(qf[k16], qreg + off);
    }

    float o[8][4];
    #pragma unroll
    for (int dt = 0; dt < 8; dt++)
        #pragma unroll
        for (int i = 0; i < 4; i++) o[dt][i] = 0.f;
    float lacc[4] = {0.f, 0.f, 0.f, 0.f};
    const float NEG_INF = __int_as_float(0xff800000);
    float mrow[2] = {NEG_INF, NEG_INF};
    const uint32_t ONE_H2 = 0x3C003C00u;
    const uint32_t onef[2] = {ONE_H2, ONE_H2};

    const int NSUP = SS / 128;  // 16 super-iterations
    for (int j = 0; j < NSUP; j++) {
        asm volatile("cp.async.wait_group 0;" ::: "memory");  // super j landed
        __syncthreads();
        if (j + 1 < NSUP) load_super(j + 1, (j + 1) & 1);

        #pragma unroll
        for (int sub = 0; sub < 2; sub++) {
            uint32_t base = sb + ((j & 1) * 2 + sub) * A_STAGE;

            // ---- S = Q K^T, fp16 accumulation ----
            // s16[nt][0] = {row r,  cols cp2..cp2+1}; s16[nt][1] = row r+8
            uint32_t s16[8][2];
            #pragma unroll
            for (int nt = 0; nt < 8; nt++) { s16[nt][0] = 0; s16[nt][1] = 0; }

            #pragma unroll
            for (int k16 = 0; k16 < 4; k16++) {
                uint32_t kf[8][2];
                #pragma unroll
                for (int nh = 0; nh < 4; nh++) {
                    int row = nh * 16 + (lane & 15);
                    uint32_t off = sw128((uint32_t)row * 128 +
                                         (k16 * 2 + (lane >> 4)) * 16);
                    uint32_t r[4];
                    ldsm_x4(r, base + off);
                    kf[nh * 2][0] = r[0]; kf[nh * 2 + 1][0] = r[1];
                    kf[nh * 2][1] = r[2]; kf[nh * 2 + 1][1] = r[3];
                }
                #pragma unroll
                for (int nt = 0; nt < 8; nt++)
                    mma16816h(s16[nt], qf[k16], kf[nt]);
            }

            // ---- softmax natively on fp16 fragments ----
            uint32_t pp[16];
            #pragma unroll
            for (int hf = 0; hf < 2; hf++) {
                __half2 mx2 = *reinterpret_cast<__half2*>(&s16[0][hf]);
                #pragma unroll
                for (int nt = 1; nt < 8; nt++)
                    mx2 = __hmax2(mx2,
                        *reinterpret_cast<__half2*>(&s16[nt][hf]));
                float mx = __half2float(
                    __hmax(__low2half(mx2), __high2half(mx2)));
                mx = fmaxf(mx, __shfl_xor_sync(0xffffffffu, mx, 1));
                mx = fmaxf(mx, __shfl_xor_sync(0xffffffffu, mx, 2));
                float mn = fmaxf(mrow[hf], mx);
                uint32_t keep = __all_sync(0xffffffffu, mn == mrow[hf]);
                if (!keep) {
                    float scale = ex2f(mrow[hf] - mn);
                    mrow[hf] = mn;
                    #pragma unroll
                    for (int dt = 0; dt < 8; dt++) {
                        o[dt][2 * hf]     *= scale;
                        o[dt][2 * hf + 1] *= scale;
                    }
                    lacc[2 * hf]     *= scale;
                    lacc[2 * hf + 1] *= scale;
                }
                __half2 mn2 = __half2half2(__float2half_rn(mn));
                #pragma unroll
                for (int nt = 0; nt < 8; nt++) {
                    __half2 d = __hsub2(
                        *reinterpret_cast<__half2*>(&s16[nt][hf]), mn2);
                    pp[4 * (nt >> 1) + (nt & 1) * 2 + hf] =
                        ex2_h2(*reinterpret_cast<uint32_t*>(&d));
                }
            }

            // ---- O += P V, l += P . 1 (fp32 accum) ----
            #pragma unroll
            for (int t = 0; t < 4; t++) {
                uint32_t vf[8][2];
                #pragma unroll
                for (int dp = 0; dp < 4; dp++) {
                    int row = t * 16 + (lane & 15);
                    uint32_t off = sw128((uint32_t)row * 128 +
                                         (dp * 2 + (lane >> 4)) * 16);
                    uint32_t r[4];
                    ldsm_x4t(r, base + 8192u + off);
                    vf[dp * 2][0] = r[0]; vf[dp * 2][1] = r[1];
                    vf[dp * 2 + 1][0] = r[2]; vf[dp * 2 + 1][1] = r[3];
                }
                #pragma unroll
                for (int dt = 0; dt < 8; dt++)
                    mma16816(o[dt], &pp[4 * t], vf[dt]);
                mma16816(lacc, &pp[4 * t], onef);
            }
        }
    }

    // ---- epilogue: ctx = O / l, written as fp16 ----
    const int r = lane >> 2, cp2 = (lane & 3) * 2;
    #pragma unroll
    for (int hf = 0; hf < 2; hf++) {
        float inv = 1.f / lacc[2 * hf];
        int row = q0 + w * 16 + r + hf * 8;
        size_t ob = ((size_t)b * SS + row) * DD + hd * 64;
        #pragma unroll
        for (int dt = 0; dt < 8; dt++) {
            float v0 = o[dt][2 * hf] * inv;
            float v1 = o[dt][2 * hf + 1] * inv;
            *reinterpret_cast<uint32_t*>(Ch + ob + dt * 8 + cp2) =
                pack_h2(v0, v1);
        }
    }
}

// ---------------------------------------------------------------------------
// Launch (launch #3 = Oproj hgemm -> new ncu info)
// ---------------------------------------------------------------------------
extern "C" void kernel_launch(void* const* d_in, const int* in_sizes, int n_in,
                              void* d_out, int out_size)
{
    const float* x  = (const float*)d_in[0];
    const float* Wq = (const float*)d_in[1];
    const float* bq = (const float*)d_in[2];
    const float* Wk = (const float*)d_in[3];
    const float* bk = (const float*)d_in[4];
    const float* Wv = (const float*)d_in[5];
    const float* bv = (const float*)d_in[6];
    const float* Wo = (const float*)d_in[7];
    const float* bo = (const float*)d_in[8];
    float* out = (float*)d_out;

    __half *xh, *qh, *kh, *vh, *ch, *wh;
    cudaGetSymbolAddress((void**)&xh, g_xh);
    cudaGetSymbolAddress((void**)&qh, g_qh);
    cudaGetSymbolAddress((void**)&kh, g_kh);
    cudaGetSymbolAddress((void**)&vh, g_vh);
    cudaGetSymbolAddress((void**)&ch, g_ch);
    cudaGetSymbolAddress((void**)&wh, g_wh);

    cudaFuncSetAttribute((const void*)hgemm<false>,
                         cudaFuncAttributeMaxDynamicSharedMemorySize, G_SMEM);
    cudaFuncSetAttribute((const void*)hgemm<true>,
                         cudaFuncAttributeMaxDynamicSharedMemorySize, G_SMEM);
    cudaFuncSetAttribute((const void*)attn_mma,
                         cudaFuncAttributeMaxDynamicSharedMemorySize, A_SMEM);

    // launch 0: fused pack (weights + x -> fp16)
    pack_all<<<12288, 256>>>(Wq, Wk, Wv, Wo, x, wh, xh);

    // launch 1: fused QKV projection (mat 0 = Q gets softmax scale folded in)
    dim3 gqkv(24, 64);
    hgemm<false><<<gqkv, 128, G_SMEM>>>(
        xh, wh, bq, bk, bv, qh, kh, vh, nullptr);

    // launch 2: attention
    dim3 ag(SS / 128, HH, BB);    // (16, 16, 4)
    attn_mma<<<ag, 256, A_SMEM>>>(qh, kh, vh, ch);

    // launch 3: output projection (fp32 out)  (ncu capture slot)
    dim3 go(8, 64);
    hgemm<true><<<go, 128, G_SMEM>>>(
        ch, wh + 3 * (size_t)DD * DD, bo, nullptr, nullptr,
        nullptr, nullptr, nullptr, out);
}